// round 14
// baseline (speedup 1.0000x reference)
#include <cuda_runtime.h>
#include <cuda_bf16.h>

// LandmarksLoss: mean((pred - true)^2), true = windowed 128x128 bell table.
//
// R14: algebraic split. (p-t)^2 = p^2 + t*(t-2p); t nonzero only in the
// <=128x128 window. Per CTA (one image), per 32-row chunk:
//   phase A: bare stream loop (LDG.128 + 4 FMA, nothing else) accumulating p^2
//   phase B: exact-bounds window loop (warp<->row, lane<->col, no per-element
//            clipping) accumulating t*(t-2p); p re-read is L1/L2-hot since the
//            same CTA just streamed those lines -> no extra DRAM traffic.
// Deterministic fused last-block final reduction.

#define H_DIM     224
#define W_DIM     224
#define HW        (H_DIM * W_DIM)      // 50176
#define ROWF4     (W_DIM / 4)          // 56
#define NF4       (HW / 4)             // 12544
#define THREADS   256
#define NWARP     (THREADS / 32)
#define CH_ROWS   32                   // rows per chunk
#define CH_F4     (CH_ROWS * ROWF4)    // 1792 f4 per chunk
#define NCHUNK    (H_DIM / CH_ROWS)    // 7
#define MAX_BL    4096
#define DELTA     128
#define HALF      64

__device__ float        g_partials[MAX_BL];
__device__ unsigned int g_count = 0;

__device__ __forceinline__ float blockReduce(float v, float* s)
{
    #pragma unroll
    for (int off = 16; off > 0; off >>= 1)
        v += __shfl_down_sync(0xFFFFFFFFu, v, off);
    const int lane = threadIdx.x & 31;
    const int wid  = threadIdx.x >> 5;
    if (lane == 0) s[wid] = v;
    __syncthreads();
    if (wid == 0) {
        v = (lane < NWARP) ? s[lane] : 0.0f;
        #pragma unroll
        for (int off = NWARP / 2; off > 0; off >>= 1)
            v += __shfl_down_sync(0xFFFFFFFFu, v, off);
    }
    return v;  // valid in thread 0
}

__global__ void __launch_bounds__(THREADS, 8)
landmarks_fused(const float* __restrict__ pred,
                const float* __restrict__ lm,
                const float* __restrict__ bell,
                float* __restrict__ out,
                int n_bl, float inv_n)
{
    const int bl = blockIdx.x;
    const float*  img  = pred + (size_t)bl * HW;
    const float4* img4 = reinterpret_cast<const float4*>(img);

    // landmarks: [...,0] = y_r, [...,1] = x_r  (round-half-to-even = jnp.round)
    const int yr = (int)rintf(__ldg(&lm[2 * bl + 0]));
    const int xr = (int)rintf(__ldg(&lm[2 * bl + 1]));
    const int xoff = HALF - xr;    // bell row = h + xoff
    const int yoff = HALF - yr;    // bell col = w + yoff

    // Exact window bounds in image coords (h,w ranges where bell term != 0).
    const int h_lo = max(0, -xoff);
    const int h_hi = min(H_DIM, DELTA - xoff);
    const int w_lo = max(0, -yoff);
    const int w_hi = min(W_DIM, DELTA - yoff);

    const int lane = threadIdx.x & 31;
    const int wid  = threadIdx.x >> 5;

    float acc = 0.0f;

    for (int c = 0; c < NCHUNK; ++c) {
        // ---- Phase A: bare stream, sum p^2 over this chunk ----
        const float4* cb = img4 + c * CH_F4;
        #pragma unroll
        for (int k = 0; k < CH_F4 / THREADS; ++k) {      // 7 iters
            const float4 p = __ldg(cb + k * THREADS + threadIdx.x);
            acc = fmaf(p.x, p.x, acc);
            acc = fmaf(p.y, p.y, acc);
            acc = fmaf(p.z, p.z, acc);
            acc = fmaf(p.w, p.w, acc);
        }

        // ---- Phase B: window cross terms for rows in this chunk ----
        const int ch_lo = max(h_lo, c * CH_ROWS);
        const int ch_hi = min(h_hi, (c + 1) * CH_ROWS);

        for (int hh = ch_lo + wid; hh < ch_hi; hh += NWARP) {
            const float* prow = img + hh * W_DIM;
            const float* brow = bell + ((hh + xoff) << 7) + yoff;
            for (int ww = w_lo + lane; ww < w_hi; ww += 32) {
                const float p = __ldg(&prow[ww]);        // L1/L2-hot
                const float t = __ldg(&brow[ww]);
                // t*(t - 2p)
                acc = fmaf(t, fmaf(-2.0f, p, t), acc);
            }
        }
    }

    __shared__ float s[NWARP];
    const float bsum = blockReduce(acc, s);

    __shared__ bool amLast;
    if (threadIdx.x == 0) {
        g_partials[bl] = bsum;
        __threadfence();
        const unsigned prev = atomicAdd(&g_count, 1u);
        amLast = (prev == (unsigned)(gridDim.x - 1));
    }
    __syncthreads();

    if (amLast) {
        // Deterministic final reduction: fixed index order every run.
        float tot = 0.0f;
        for (int i = threadIdx.x; i < n_bl; i += THREADS)
            tot += __ldcg(&g_partials[i]);
        __syncthreads();   // reuse s[] safely
        const float t = blockReduce(tot, s);
        if (threadIdx.x == 0) {
            out[0] = t * inv_n;
            g_count = 0;   // reset for next graph replay
        }
    }
}

extern "C" void kernel_launch(void* const* d_in, const int* in_sizes, int n_in,
                              void* d_out, int out_size)
{
    const float* pred = (const float*)d_in[0];  // (B, L, 224, 224)
    const float* lm   = (const float*)d_in[1];  // (B, L, 2)
    const float* bell = (const float*)d_in[2];  // (128, 128)
    float* out = (float*)d_out;

    const int n_bl = in_sizes[1] / 2;           // B*L = 1088
    const float inv_n = 1.0f / ((float)n_bl * (float)HW);

    landmarks_fused<<<n_bl, THREADS>>>(pred, lm, bell, out, n_bl, inv_n);
}